// round 12
// baseline (speedup 1.0000x reference)
#include <cuda_runtime.h>
#include <math.h>

#define S_LEN 1024
#define B_DIM 64
#define NBLK  128
#define GRP_CTAS 32

typedef unsigned long long u64;

// ---------------- f32x2 helpers (sm_100+) -----------------------------------
__device__ __forceinline__ u64 dupf(float x) {
    u64 r; unsigned xi = __float_as_uint(x);
    asm("mov.b64 %0, {%1, %1};" : "=l"(r) : "r"(xi));
    return r;
}
__device__ __forceinline__ void fma2(u64& d, u64 a, u64 b) {
    asm("fma.rn.f32x2 %0, %1, %2, %0;" : "+l"(d) : "l"(a), "l"(b));
}
__device__ __forceinline__ u64 add2(u64 a, u64 b) {
    u64 d; asm("add.rn.f32x2 %0, %1, %2;" : "=l"(d) : "l"(a), "l"(b));
    return d;
}
__device__ __forceinline__ void unpk(u64 p, float& lo, float& hi) {
    unsigned a, b;
    asm("mov.b64 {%0, %1}, %2;" : "=r"(a), "=r"(b) : "l"(p));
    lo = __uint_as_float(a); hi = __uint_as_float(b);
}

// swizzled chunk column for 16-row tiles
__device__ __forceinline__ int swz2(int b, int c) {
    return c ^ ((b >> 1) & 7) ^ ((c >> 4) & 7) ^ ((b & 1) << 2);
}

// L1-bypassing loads for globals with intra-launch address reuse
__device__ __forceinline__ float4 ldcg4(const float4* p) {
    float4 v;
    asm volatile("ld.global.cg.v4.f32 {%0,%1,%2,%3}, [%4];"
                 : "=f"(v.x), "=f"(v.y), "=f"(v.z), "=f"(v.w) : "l"(p));
    return v;
}
__device__ __forceinline__ float2 ldcg2(const float* p) {
    float2 v;
    asm volatile("ld.global.cg.v2.f32 {%0,%1}, [%2];"
                 : "=f"(v.x), "=f"(v.y) : "l"(p));
    return v;
}

// ---------------- device scratch --------------------------------------------
__device__ float g_pre[S_LEN * B_DIM * 1536];   // xz|xr|xh preactivations
__device__ float g_WT[512 * 1536];              // [k][n] input weights (k-major)
__device__ float g_Uzrp[32 * 512 * 32];         // packed [cl][k][32n] zr weights
__device__ float g_Uhp[32 * 512 * 16];          // packed [cl][k][16n] h weights
__device__ float g_wbias[1536];
__device__ float g_ubias[1536];
__device__ float g_z[2][B_DIM * 512];           // parity-buffered gate values
__device__ float g_rh[2][B_DIM * 512];
__device__ unsigned g_flags[NBLK * 32];         // per-CTA flags, 128B stride

// ---------------- pack + flag reset -----------------------------------------
__global__ void pack_kernel(const float* Wz, const float* bz, const float* Uz, const float* ubz,
                            const float* Wr, const float* br, const float* Ur, const float* ubr,
                            const float* Wh, const float* bh, const float* Uh, const float* ubh) {
    int stride = gridDim.x * blockDim.x;
    int t = blockIdx.x * blockDim.x + threadIdx.x;
    for (int idx = t; idx < NBLK * 32; idx += stride) g_flags[idx] = 0u;
    for (int idx = t; idx < 512 * 1536; idx += stride) {
        int k = idx / 1536, n = idx % 1536;
        const float* W = (n < 512) ? Wz : (n < 1024 ? Wr : Wh);
        g_WT[idx] = W[(n & 511) * 512 + k];
    }
    for (int idx = t; idx < 32 * 512 * 32; idx += stride) {
        int cl = idx >> 14, k = (idx >> 5) & 511, nn = idx & 31;
        int n = cl * 32 + nn;
        g_Uzrp[idx] = (n < 512) ? Uz[n * 512 + k] : Ur[(n - 512) * 512 + k];
    }
    for (int idx = t; idx < 32 * 512 * 16; idx += stride) {
        int cl = idx >> 13, k = (idx >> 4) & 511, nn = idx & 15;
        g_Uhp[idx] = Uh[(cl * 16 + nn) * 512 + k];
    }
    for (int idx = t; idx < 1536; idx += stride) {
        int n = idx & 511;
        g_wbias[idx] = (idx < 512) ? bz[n] : (idx < 1024 ? br[n] : bh[n]);
        g_ubias[idx] = (idx < 512) ? ubz[n] : (idx < 1024 ? ubr[n] : ubh[n]);
    }
}

// ---------------- input projection GEMM (f32x2, double-buffered) ------------
__global__ __launch_bounds__(256) void input_gemm(const float* __restrict__ x) {
    __shared__ float As[2][16 * 132];
    __shared__ float Bs[2][16 * 64];
    int tid = threadIdx.x;
    int tx = tid & 15, ty = tid >> 4;
    int m0 = blockIdx.y * 128;
    int n0 = blockIdx.x * 64;

    const int fA0 = tid,       mA0 = fA0 >> 2, kqA0 = fA0 & 3;
    const int fA1 = 256 + tid, mA1 = fA1 >> 2, kqA1 = fA1 & 3;
    const int kB  = tid >> 4,  nqB = tid & 15;
    const float* xA0 = x + (m0 + mA0) * 512 + kqA0 * 4;
    const float* xA1 = x + (m0 + mA1) * 512 + kqA1 * 4;
    const float* wB  = g_WT + kB * 1536 + n0 + nqB * 4;

    u64 acc[8][2];
#pragma unroll
    for (int i = 0; i < 8; i++) { acc[i][0] = 0ull; acc[i][1] = 0ull; }

    {
        float4 a0 = *(const float4*)(xA0);
        float4 a1 = *(const float4*)(xA1);
        float4 b0 = *(const float4*)(wB);
        As[0][(kqA0 * 4 + 0) * 132 + mA0] = a0.x;
        As[0][(kqA0 * 4 + 1) * 132 + mA0] = a0.y;
        As[0][(kqA0 * 4 + 2) * 132 + mA0] = a0.z;
        As[0][(kqA0 * 4 + 3) * 132 + mA0] = a0.w;
        As[0][(kqA1 * 4 + 0) * 132 + mA1] = a1.x;
        As[0][(kqA1 * 4 + 1) * 132 + mA1] = a1.y;
        As[0][(kqA1 * 4 + 2) * 132 + mA1] = a1.z;
        As[0][(kqA1 * 4 + 3) * 132 + mA1] = a1.w;
        *(float4*)&Bs[0][kB * 64 + nqB * 4] = b0;
    }
    __syncthreads();

    for (int kt = 0; kt < 32; kt++) {
        int cur = kt & 1;
        float4 a0n, a1n, b0n;
        if (kt < 31) {
            int k0 = (kt + 1) * 16;
            a0n = *(const float4*)(xA0 + k0);
            a1n = *(const float4*)(xA1 + k0);
            b0n = *(const float4*)(wB + (unsigned)k0 * 1536);
        }
        const float* Ac = As[cur];
        const float* Bc = Bs[cur];
#pragma unroll
        for (int kk = 0; kk < 16; kk++) {
            float4 a0 = *(const float4*)&Ac[kk * 132 + ty * 8];
            float4 a1 = *(const float4*)&Ac[kk * 132 + ty * 8 + 4];
            ulonglong2 bb = *(const ulonglong2*)&Bc[kk * 64 + tx * 4];
            u64 d0 = dupf(a0.x), d1 = dupf(a0.y), d2 = dupf(a0.z), d3 = dupf(a0.w);
            u64 d4 = dupf(a1.x), d5 = dupf(a1.y), d6 = dupf(a1.z), d7 = dupf(a1.w);
            fma2(acc[0][0], d0, bb.x); fma2(acc[0][1], d0, bb.y);
            fma2(acc[1][0], d1, bb.x); fma2(acc[1][1], d1, bb.y);
            fma2(acc[2][0], d2, bb.x); fma2(acc[2][1], d2, bb.y);
            fma2(acc[3][0], d3, bb.x); fma2(acc[3][1], d3, bb.y);
            fma2(acc[4][0], d4, bb.x); fma2(acc[4][1], d4, bb.y);
            fma2(acc[5][0], d5, bb.x); fma2(acc[5][1], d5, bb.y);
            fma2(acc[6][0], d6, bb.x); fma2(acc[6][1], d6, bb.y);
            fma2(acc[7][0], d7, bb.x); fma2(acc[7][1], d7, bb.y);
        }
        if (kt < 31) {
            int nxt = cur ^ 1;
            As[nxt][(kqA0 * 4 + 0) * 132 + mA0] = a0n.x;
            As[nxt][(kqA0 * 4 + 1) * 132 + mA0] = a0n.y;
            As[nxt][(kqA0 * 4 + 2) * 132 + mA0] = a0n.z;
            As[nxt][(kqA0 * 4 + 3) * 132 + mA0] = a0n.w;
            As[nxt][(kqA1 * 4 + 0) * 132 + mA1] = a1n.x;
            As[nxt][(kqA1 * 4 + 1) * 132 + mA1] = a1n.y;
            As[nxt][(kqA1 * 4 + 2) * 132 + mA1] = a1n.z;
            As[nxt][(kqA1 * 4 + 3) * 132 + mA1] = a1n.w;
            *(float4*)&Bs[nxt][kB * 64 + nqB * 4] = b0n;
            __syncthreads();
        }
    }
#pragma unroll
    for (int i = 0; i < 8; i++) {
        int m = m0 + ty * 8 + i;
        int n = n0 + tx * 4;
        float4 o;
        float v0, v1, v2, v3;
        unpk(acc[i][0], v0, v1);
        unpk(acc[i][1], v2, v3);
        o.x = v0 + g_wbias[n + 0];
        o.y = v1 + g_wbias[n + 1];
        o.z = v2 + g_wbias[n + 2];
        o.w = v3 + g_wbias[n + 3];
        *(float4*)&g_pre[m * 1536 + n] = o;
    }
}

// ---------------- persistent GRU scan: fine-grained producer waits ----------
// 4 groups x 32 CTAs; group g owns batch rows [g*16, g*16+16).
// Flags: one monotone counter per CTA: 2s+1 = z/rh written, 2s+2 = out written.
// Warp w waits only on its data producers (4 for h, 2+1 for rh/z); full
// fan-in resolves at the reduce __syncthreads. g_rh/g_z parity-buffered;
// their consumer loads use ld.global.cg (L1-bypass) because the addresses
// are re-read every 2 steps within one launch.
__global__ __launch_bounds__(256, 1) void gru_scan(const float* __restrict__ h0,
                                                   float* out) {
    extern __shared__ float smem[];
    float4* hs4 = (float4*)smem;                // [16][128] chunks swizzled, 32KB
    float4* rs4 = hs4 + 2048;                   // [16][128] chunks swizzled, 32KB
    float*  us  = smem + 16384;                 // [512][32]  64KB zr weights
    float*  u2  = smem + 32768;                 // [512][16]  32KB h  weights
    u64*    red = (u64*)(smem + 40960);         // 2048 u64   16KB

    const int tid  = threadIdx.x;
    const int cta  = blockIdx.x;
    const int w    = tid >> 5;
    const int lane = tid & 31;
    const int g    = cta >> 5;
    const int cl   = cta & 31;
    const int gbase = cta & ~(GRP_CTAS - 1);
    const int gb0  = g * 16;                    // group batch base

    // --- resident weights ---
    {
        const float* up1 = g_Uzrp + cl * 16384;
#pragma unroll
        for (int i = 0; i < 16; i++) {
            int off = (i * 256 + tid) * 4;
            *(float4*)&us[off] = *(const float4*)(up1 + off);
        }
        const float* up2 = g_Uhp + cl * 8192;
#pragma unroll
        for (int i = 0; i < 8; i++) {
            int off = (i * 256 + tid) * 4;
            *(float4*)&u2[off] = *(const float4*)(up2 + off);
        }
    }

    // --- epilogue constants ---
    const int b1l = tid >> 4;                  // P1 local b (0..15)
    const int b1  = gb0 + b1l;
    const int n1  = cl * 32 + (tid & 15) * 2;  // P1 n (0..1022)
    const float2 ub1 = *(const float2*)&g_ubias[n1];
    const int o1c = b1l * 16 + ((tid & 15) ^ ((b1l >> 2) << 1));
    const int o2  = tid & 127;
    const int b2l = o2 >> 3;
    const int b2  = gb0 + b2l;
    const int n2  = cl * 16 + (o2 & 7) * 2;
    const float2 ub2 = *(const float2*)&g_ubias[1024 + n2];
    const int o2c = b2l * 8 + ((o2 & 7) ^ ((b2l >> 1) & 3));

    // --- compute-lane constants ---
    const int bg  = lane >> 3;   // P1: 4 b-groups of 4 rows
    const int ng  = lane & 7;    // P1: 8 n-groups of 4 cols
    const int bg2 = lane >> 2;   // P2: 8 b-groups of 2 rows
    const int ng2 = lane & 3;    // P2: 4 n-groups of 4 cols
    // warp-private tile-load lane map: r = q*2 + rh2, c = w*16 + wl
    const int wl  = lane & 15;
    const int rh2 = lane >> 4;
    const int cch = w * 16 + wl;

    // --- producer sets for this warp / CTA ---
    const int hprod  = gbase + w * 4;          // h producers: +0..+3
    const int rprod  = gbase + 16 + w * 2;     // rh producers: +0..+1
    const int zprod  = gbase + (cl >> 1);      // z producer for this CTA's slice

    // --- prefetch step-0 epilogue operands ---
    float2 pre1 = *(const float2*)&g_pre[b1 * 1536 + n1];
    float2 pre2 = make_float2(0.f, 0.f);
    if (tid < 128)
        pre2 = *(const float2*)&g_pre[b2 * 1536 + 1024 + n2];

    for (int s = 0; s < S_LEN; s++) {
        const float* hprev = (s == 0) ? h0 : (out + (s - 1) * (B_DIM * 512));
        const int par = s & 1;

        // ===== per-warp wait: my 4 h-producers wrote out[s-1] (>= 2s) =====
        {
            unsigned tgt = (unsigned)(2 * s);
            if (lane < 4) {
                const unsigned* fp = &g_flags[(hprod + lane) * 32];
                unsigned v;
                do {
                    asm volatile("ld.acquire.gpu.u32 %0, [%1];"
                                 : "=r"(v) : "l"(fp) : "memory");
                } while (v < tgt);
            }
            __syncwarp();
        }

        // --- warp-private load of h tile chunks [w*16, w*16+16) ---
        {
            const float4* hp4 = (const float4*)(hprev + gb0 * 512);
#pragma unroll
            for (int q = 0; q < 8; q++) {
                int r = q * 2 + rh2;
                hs4[r * 128 + swz2(r, cch)] = hp4[r * 128 + cch];
            }
            __syncwarp();
        }

        // ================= Phase 1: zr = sigmoid(pre + h@Uzr^T + ub) ========
        {
            u64 acc[4][2];
#pragma unroll
            for (int i = 0; i < 4; i++) { acc[i][0] = 0ull; acc[i][1] = 0ull; }
            const float4* hr0 = hs4 + (bg * 4 + 0) * 128;
            const float4* hr1 = hs4 + (bg * 4 + 1) * 128;
            const float4* hr2 = hs4 + (bg * 4 + 2) * 128;
            const float4* hr3 = hs4 + (bg * 4 + 3) * 128;
            const int m0 = bg * 2, m1 = (bg * 2) ^ 4;
            const int m2 = bg * 2 + 1, m3 = (bg * 2 + 1) ^ 4;
            const float* upc = us + ng * 4;
#pragma unroll
            for (int cc = 0; cc < 16; cc++) {
                int cb = w * 16 + cc;
                int cx = cb ^ w;
                float4 hv0 = hr0[cx ^ m0];
                float4 hv1 = hr1[cx ^ m1];
                float4 hv2 = hr2[cx ^ m2];
                float4 hv3 = hr3[cx ^ m3];
                const float* ub = upc + cb * 128;
                ulonglong2 uu0 = *(const ulonglong2*)(ub);
                ulonglong2 uu1 = *(const ulonglong2*)(ub + 32);
                ulonglong2 uu2 = *(const ulonglong2*)(ub + 64);
                ulonglong2 uu3 = *(const ulonglong2*)(ub + 96);
                u64 d;
                d = dupf(hv0.x); fma2(acc[0][0], d, uu0.x); fma2(acc[0][1], d, uu0.y);
                d = dupf(hv1.x); fma2(acc[1][0], d, uu0.x); fma2(acc[1][1], d, uu0.y);
                d = dupf(hv2.x); fma2(acc[2][0], d, uu0.x); fma2(acc[2][1], d, uu0.y);
                d = dupf(hv3.x); fma2(acc[3][0], d, uu0.x); fma2(acc[3][1], d, uu0.y);
                d = dupf(hv0.y); fma2(acc[0][0], d, uu1.x); fma2(acc[0][1], d, uu1.y);
                d = dupf(hv1.y); fma2(acc[1][0], d, uu1.x); fma2(acc[1][1], d, uu1.y);
                d = dupf(hv2.y); fma2(acc[2][0], d, uu1.x); fma2(acc[2][1], d, uu1.y);
                d = dupf(hv3.y); fma2(acc[3][0], d, uu1.x); fma2(acc[3][1], d, uu1.y);
                d = dupf(hv0.z); fma2(acc[0][0], d, uu2.x); fma2(acc[0][1], d, uu2.y);
                d = dupf(hv1.z); fma2(acc[1][0], d, uu2.x); fma2(acc[1][1], d, uu2.y);
                d = dupf(hv2.z); fma2(acc[2][0], d, uu2.x); fma2(acc[2][1], d, uu2.y);
                d = dupf(hv3.z); fma2(acc[3][0], d, uu2.x); fma2(acc[3][1], d, uu2.y);
                d = dupf(hv0.w); fma2(acc[0][0], d, uu3.x); fma2(acc[0][1], d, uu3.y);
                d = dupf(hv1.w); fma2(acc[1][0], d, uu3.x); fma2(acc[1][1], d, uu3.y);
                d = dupf(hv2.w); fma2(acc[2][0], d, uu3.x); fma2(acc[2][1], d, uu3.y);
                d = dupf(hv3.w); fma2(acc[3][0], d, uu3.x); fma2(acc[3][1], d, uu3.y);
            }
            int rbase = w * 256;
#pragma unroll
            for (int i = 0; i < 4; i++) {
                int bl = bg * 4 + i;
                red[rbase + bl * 16 + ((ng * 2)     ^ (bg << 1))] = acc[i][0];
                red[rbase + bl * 16 + ((ng * 2 + 1) ^ (bg << 1))] = acc[i][1];
            }
            __syncthreads();   // NOTE: implies all 32 group flags >= 2s
            {
                u64 ssum = red[o1c];
#pragma unroll
                for (int p = 1; p < 8; p++) ssum = add2(ssum, red[p * 256 + o1c]);
                float v0s, v1s; unpk(ssum, v0s, v1s);
                float a0 = pre1.x + v0s + ub1.x;
                float a1 = pre1.y + v1s + ub1.y;
                float v0 = 1.f / (1.f + __expf(-a0));
                float v1 = 1.f / (1.f + __expf(-a1));
                if (cl < 16) {
                    *(float2*)&g_z[par][b1 * 512 + n1] = make_float2(v0, v1);
                } else {
                    int j = n1 - 512;
                    int c = j >> 2;
                    const float* ch = (const float*)&hs4[b1l * 128 + swz2(b1l, c)];
                    *(float2*)&g_rh[par][b1 * 512 + j] =
                        make_float2(v0 * ch[j & 3], v1 * ch[(j & 3) + 1]);
                }
            }
        }
        __syncthreads();       // all z/rh stores done
        if (tid == 0) {
            asm volatile("st.release.gpu.u32 [%0], %1;"
                         :: "l"(&g_flags[cta * 32]), "r"((unsigned)(2 * s + 1)) : "memory");
        }

        // ===== per-warp wait: my 2 rh-producers + z-producer (>= 2s+1) =====
        {
            unsigned tgt = (unsigned)(2 * s + 1);
            if (lane < 3) {
                int p = (lane < 2) ? (rprod + lane) : zprod;
                const unsigned* fp = &g_flags[p * 32];
                unsigned v;
                do {
                    asm volatile("ld.acquire.gpu.u32 %0, [%1];"
                                 : "=r"(v) : "l"(fp) : "memory");
                } while (v < tgt);
            }
            __syncwarp();
        }

        // --- prefetch z for P2 epilogue (L1-bypass: parity-reused address) ---
        float2 zf = make_float2(0.f, 0.f);
        if (tid < 128) zf = ldcg2(&g_z[par][b2 * 512 + n2]);

        // --- warp-private load of rh tile chunks (L1-bypass) ---
        {
            const float4* rp4 = (const float4*)(g_rh[par] + gb0 * 512);
#pragma unroll
            for (int q = 0; q < 8; q++) {
                int r = q * 2 + rh2;
                rs4[r * 128 + swz2(r, cch)] = ldcg4(rp4 + r * 128 + cch);
            }
            __syncwarp();
        }

        // ================= Phase 2: h~ = tanh(pre + rh@Uh^T + ub) ===========
        {
            u64 acc[2][2];
            acc[0][0] = acc[0][1] = acc[1][0] = acc[1][1] = 0ull;
            const float4* rr0 = rs4 + (bg2 * 2 + 0) * 128;
            const float4* rr1 = rs4 + (bg2 * 2 + 1) * 128;
            const int q0 = bg2, q1 = bg2 ^ 4;
            const float* upc = u2 + ng2 * 4;
#pragma unroll
            for (int cc = 0; cc < 16; cc++) {
                int cb = w * 16 + cc;
                int cx = cb ^ w;
                float4 rv0 = rr0[cx ^ q0];
                float4 rv1 = rr1[cx ^ q1];
                const float* ub = upc + cb * 64;
                ulonglong2 uu0 = *(const ulonglong2*)(ub);
                ulonglong2 uu1 = *(const ulonglong2*)(ub + 16);
                ulonglong2 uu2 = *(const ulonglong2*)(ub + 32);
                ulonglong2 uu3 = *(const ulonglong2*)(ub + 48);
                u64 d;
                d = dupf(rv0.x); fma2(acc[0][0], d, uu0.x); fma2(acc[0][1], d, uu0.y);
                d = dupf(rv1.x); fma2(acc[1][0], d, uu0.x); fma2(acc[1][1], d, uu0.y);
                d = dupf(rv0.y); fma2(acc[0][0], d, uu1.x); fma2(acc[0][1], d, uu1.y);
                d = dupf(rv1.y); fma2(acc[1][0], d, uu1.x); fma2(acc[1][1], d, uu1.y);
                d = dupf(rv0.z); fma2(acc[0][0], d, uu2.x); fma2(acc[0][1], d, uu2.y);
                d = dupf(rv1.z); fma2(acc[1][0], d, uu2.x); fma2(acc[1][1], d, uu2.y);
                d = dupf(rv0.w); fma2(acc[0][0], d, uu3.x); fma2(acc[0][1], d, uu3.y);
                d = dupf(rv1.w); fma2(acc[1][0], d, uu3.x); fma2(acc[1][1], d, uu3.y);
            }
            int rbase = w * 128;
#pragma unroll
            for (int i = 0; i < 2; i++) {
                int bl = bg2 * 2 + i;
                red[rbase + bl * 8 + ((ng2 * 2)     ^ (bg2 & 3))] = acc[i][0];
                red[rbase + bl * 8 + ((ng2 * 2 + 1) ^ (bg2 & 3))] = acc[i][1];
            }
            __syncthreads();
            if (tid < 128) {
                u64 ssum = red[o2c];
#pragma unroll
                for (int p = 1; p < 8; p++) ssum = add2(ssum, red[p * 128 + o2c]);
                float v0s, v1s; unpk(ssum, v0s, v1s);
                int c = n2 >> 2;
                const float* ch = (const float*)&hs4[b2l * 128 + swz2(b2l, c)];
                float hp0 = ch[n2 & 3], hp1 = ch[(n2 & 3) + 1];
                float a0 = pre2.x + v0s + ub2.x;
                float a1 = pre2.y + v1s + ub2.y;
                float e0 = __expf(2.f * a0), e1 = __expf(2.f * a1);
                float th0 = 1.f - 2.f / (e0 + 1.f);
                float th1 = 1.f - 2.f / (e1 + 1.f);
                float hn0 = hp0 + zf.x * (th0 - hp0);
                float hn1 = hp1 + zf.y * (th1 - hp1);
                float2 o = make_float2(hn0, hn1);
                *(float2*)&out[s * (B_DIM * 512) + b2 * 512 + n2] = o;
                if (s == S_LEN - 1)
                    *(float2*)&out[S_LEN * (B_DIM * 512) + b2 * 512 + n2] = o;
            }
        }
        __syncthreads();       // out stores + hs4/rs4 epilogue reads done
        if (tid == 0) {
            asm volatile("st.release.gpu.u32 [%0], %1;"
                         :: "l"(&g_flags[cta * 32]), "r"((unsigned)(2 * s + 2)) : "memory");
        }
        // next-step epilogue prefetch in the release/wait shadow
        {
            int sp = (s + 1 < S_LEN) ? (s + 1) : s;
            pre1 = *(const float2*)&g_pre[(sp * 64 + b1) * 1536 + n1];
            if (tid < 128)
                pre2 = *(const float2*)&g_pre[(sp * 64 + b2) * 1536 + 1024 + n2];
        }
    }
}

// ---------------- launch ----------------------------------------------------
extern "C" void kernel_launch(void* const* d_in, const int* in_sizes, int n_in,
                              void* d_out, int out_size) {
    (void)in_sizes; (void)n_in; (void)out_size;
    const float* x    = (const float*)d_in[0];
    const float* h0   = (const float*)d_in[1];
    const float* Wz_w = (const float*)d_in[2];
    const float* Wz_b = (const float*)d_in[3];
    const float* Uz_w = (const float*)d_in[4];
    const float* Uz_b = (const float*)d_in[5];
    const float* Wr_w = (const float*)d_in[6];
    const float* Wr_b = (const float*)d_in[7];
    const float* Ur_w = (const float*)d_in[8];
    const float* Ur_b = (const float*)d_in[9];
    const float* Wh_w = (const float*)d_in[10];
    const float* Wh_b = (const float*)d_in[11];
    const float* Uh_w = (const float*)d_in[12];
    const float* Uh_b = (const float*)d_in[13];
    float* out = (float*)d_out;

    static int smem_set = 0;
    if (!smem_set) {
        cudaFuncSetAttribute(gru_scan, cudaFuncAttributeMaxDynamicSharedMemorySize,
                             180224);
        smem_set = 1;
    }

    pack_kernel<<<256, 256>>>(Wz_w, Wz_b, Uz_w, Uz_b,
                              Wr_w, Wr_b, Ur_w, Ur_b,
                              Wh_w, Wh_b, Uh_w, Uh_b);
    input_gemm<<<dim3(24, 512), 256>>>(x);
    gru_scan<<<NBLK, 256, 180224>>>(h0, out);
}

// round 14
// speedup vs baseline: 1.0330x; 1.0330x over previous
#include <cuda_runtime.h>
#include <math.h>

#define S_LEN 1024
#define B_DIM 64
#define NBLK  128
#define GRP_CTAS 32

typedef unsigned long long u64;

// ---------------- f32x2 helpers (sm_100+) -----------------------------------
__device__ __forceinline__ u64 dupf(float x) {
    u64 r; unsigned xi = __float_as_uint(x);
    asm("mov.b64 %0, {%1, %1};" : "=l"(r) : "r"(xi));
    return r;
}
__device__ __forceinline__ void fma2(u64& d, u64 a, u64 b) {
    asm("fma.rn.f32x2 %0, %1, %2, %0;" : "+l"(d) : "l"(a), "l"(b));
}
__device__ __forceinline__ u64 add2(u64 a, u64 b) {
    u64 d; asm("add.rn.f32x2 %0, %1, %2;" : "=l"(d) : "l"(a), "l"(b));
    return d;
}
__device__ __forceinline__ void unpk(u64 p, float& lo, float& hi) {
    unsigned a, b;
    asm("mov.b64 {%0, %1}, %2;" : "=r"(a), "=r"(b) : "l"(p));
    lo = __uint_as_float(a); hi = __uint_as_float(b);
}

// swizzled chunk column for 16-row tiles
__device__ __forceinline__ int swz2(int b, int c) {
    return c ^ ((b >> 1) & 7) ^ ((c >> 4) & 7) ^ ((b & 1) << 2);
}

// L1-bypassing loads for globals with intra-launch address reuse
__device__ __forceinline__ float4 ldcg4(const float4* p) {
    float4 v;
    asm volatile("ld.global.cg.v4.f32 {%0,%1,%2,%3}, [%4];"
                 : "=f"(v.x), "=f"(v.y), "=f"(v.z), "=f"(v.w) : "l"(p));
    return v;
}
__device__ __forceinline__ float2 ldcg2(const float* p) {
    float2 v;
    asm volatile("ld.global.cg.v2.f32 {%0,%1}, [%2];"
                 : "=f"(v.x), "=f"(v.y) : "l"(p));
    return v;
}

// ---------------- device scratch --------------------------------------------
__device__ float g_pre[S_LEN * B_DIM * 1536];   // xz|xr|xh preactivations
__device__ float g_WT[512 * 1536];              // [k][n] input weights (k-major)
__device__ float g_Uzrp[32 * 512 * 32];         // packed [cl][k][32n] zr weights
__device__ float g_Uhp[32 * 512 * 16];          // packed [cl][k][16n] h weights
__device__ float g_wbias[1536];
__device__ float g_ubias[1536];
__device__ float g_z[2][B_DIM * 512];           // parity-buffered gate values
__device__ float g_rh[2][B_DIM * 512];
__device__ unsigned g_flags[NBLK * 32];         // per-CTA flags, 128B stride

// ---------------- pack + flag reset -----------------------------------------
__global__ void pack_kernel(const float* Wz, const float* bz, const float* Uz, const float* ubz,
                            const float* Wr, const float* br, const float* Ur, const float* ubr,
                            const float* Wh, const float* bh, const float* Uh, const float* ubh) {
    int stride = gridDim.x * blockDim.x;
    int t = blockIdx.x * blockDim.x + threadIdx.x;
    for (int idx = t; idx < NBLK * 32; idx += stride) g_flags[idx] = 0u;
    for (int idx = t; idx < 512 * 1536; idx += stride) {
        int k = idx / 1536, n = idx % 1536;
        const float* W = (n < 512) ? Wz : (n < 1024 ? Wr : Wh);
        g_WT[idx] = W[(n & 511) * 512 + k];
    }
    for (int idx = t; idx < 32 * 512 * 32; idx += stride) {
        int cl = idx >> 14, k = (idx >> 5) & 511, nn = idx & 31;
        int n = cl * 32 + nn;
        g_Uzrp[idx] = (n < 512) ? Uz[n * 512 + k] : Ur[(n - 512) * 512 + k];
    }
    for (int idx = t; idx < 32 * 512 * 16; idx += stride) {
        int cl = idx >> 13, k = (idx >> 4) & 511, nn = idx & 15;
        g_Uhp[idx] = Uh[(cl * 16 + nn) * 512 + k];
    }
    for (int idx = t; idx < 1536; idx += stride) {
        int n = idx & 511;
        g_wbias[idx] = (idx < 512) ? bz[n] : (idx < 1024 ? br[n] : bh[n]);
        g_ubias[idx] = (idx < 512) ? ubz[n] : (idx < 1024 ? ubr[n] : ubh[n]);
    }
}

// ---------------- input projection GEMM (f32x2, double-buffered, BN=128) ----
// C[65536,1536] = X[65536,512] * WT[512,1536]; BM=128,BN=128,BK=16; 8x8/thread.
// One A tile feeds two 64-wide B half-tiles (same per-element fma order as
// before => bit-identical output).
__global__ __launch_bounds__(256, 2) void input_gemm(const float* __restrict__ x) {
    __shared__ float As[2][16 * 132];
    __shared__ float Bs[2][16 * 128];
    int tid = threadIdx.x;
    int tx = tid & 15, ty = tid >> 4;
    int m0 = blockIdx.y * 128;
    int n0 = blockIdx.x * 128;

    const int fA0 = tid,       mA0 = fA0 >> 2, kqA0 = fA0 & 3;
    const int fA1 = 256 + tid, mA1 = fA1 >> 2, kqA1 = fA1 & 3;
    const int kB  = tid >> 4,  nqB = tid & 15;
    const float* xA0 = x + (m0 + mA0) * 512 + kqA0 * 4;
    const float* xA1 = x + (m0 + mA1) * 512 + kqA1 * 4;
    const float* wB0 = g_WT + kB * 1536 + n0 + nqB * 4;
    const float* wB1 = wB0 + 64;

    u64 acc[8][4];
#pragma unroll
    for (int i = 0; i < 8; i++)
#pragma unroll
        for (int j = 0; j < 4; j++) acc[i][j] = 0ull;

    {
        float4 a0 = *(const float4*)(xA0);
        float4 a1 = *(const float4*)(xA1);
        float4 b0 = *(const float4*)(wB0);
        float4 b1 = *(const float4*)(wB1);
        As[0][(kqA0 * 4 + 0) * 132 + mA0] = a0.x;
        As[0][(kqA0 * 4 + 1) * 132 + mA0] = a0.y;
        As[0][(kqA0 * 4 + 2) * 132 + mA0] = a0.z;
        As[0][(kqA0 * 4 + 3) * 132 + mA0] = a0.w;
        As[0][(kqA1 * 4 + 0) * 132 + mA1] = a1.x;
        As[0][(kqA1 * 4 + 1) * 132 + mA1] = a1.y;
        As[0][(kqA1 * 4 + 2) * 132 + mA1] = a1.z;
        As[0][(kqA1 * 4 + 3) * 132 + mA1] = a1.w;
        *(float4*)&Bs[0][kB * 128 + nqB * 4] = b0;
        *(float4*)&Bs[0][kB * 128 + 64 + nqB * 4] = b1;
    }
    __syncthreads();

    for (int kt = 0; kt < 32; kt++) {
        int cur = kt & 1;
        float4 a0n, a1n, b0n, b1n;
        if (kt < 31) {
            int k0 = (kt + 1) * 16;
            a0n = *(const float4*)(xA0 + k0);
            a1n = *(const float4*)(xA1 + k0);
            b0n = *(const float4*)(wB0 + (unsigned)k0 * 1536);
            b1n = *(const float4*)(wB1 + (unsigned)k0 * 1536);
        }
        const float* Ac = As[cur];
        const float* Bc = Bs[cur];
#pragma unroll
        for (int kk = 0; kk < 16; kk++) {
            float4 a0 = *(const float4*)&Ac[kk * 132 + ty * 8];
            float4 a1 = *(const float4*)&Ac[kk * 132 + ty * 8 + 4];
            ulonglong2 bb0 = *(const ulonglong2*)&Bc[kk * 128 + tx * 4];
            ulonglong2 bb1 = *(const ulonglong2*)&Bc[kk * 128 + 64 + tx * 4];
            u64 d0 = dupf(a0.x), d1 = dupf(a0.y), d2 = dupf(a0.z), d3 = dupf(a0.w);
            u64 d4 = dupf(a1.x), d5 = dupf(a1.y), d6 = dupf(a1.z), d7 = dupf(a1.w);
            fma2(acc[0][0], d0, bb0.x); fma2(acc[0][1], d0, bb0.y);
            fma2(acc[1][0], d1, bb0.x); fma2(acc[1][1], d1, bb0.y);
            fma2(acc[2][0], d2, bb0.x); fma2(acc[2][1], d2, bb0.y);
            fma2(acc[3][0], d3, bb0.x); fma2(acc[3][1], d3, bb0.y);
            fma2(acc[4][0], d4, bb0.x); fma2(acc[4][1], d4, bb0.y);
            fma2(acc[5][0], d5, bb0.x); fma2(acc[5][1], d5, bb0.y);
            fma2(acc[6][0], d6, bb0.x); fma2(acc[6][1], d6, bb0.y);
            fma2(acc[7][0], d7, bb0.x); fma2(acc[7][1], d7, bb0.y);
            fma2(acc[0][2], d0, bb1.x); fma2(acc[0][3], d0, bb1.y);
            fma2(acc[1][2], d1, bb1.x); fma2(acc[1][3], d1, bb1.y);
            fma2(acc[2][2], d2, bb1.x); fma2(acc[2][3], d2, bb1.y);
            fma2(acc[3][2], d3, bb1.x); fma2(acc[3][3], d3, bb1.y);
            fma2(acc[4][2], d4, bb1.x); fma2(acc[4][3], d4, bb1.y);
            fma2(acc[5][2], d5, bb1.x); fma2(acc[5][3], d5, bb1.y);
            fma2(acc[6][2], d6, bb1.x); fma2(acc[6][3], d6, bb1.y);
            fma2(acc[7][2], d7, bb1.x); fma2(acc[7][3], d7, bb1.y);
        }
        if (kt < 31) {
            int nxt = cur ^ 1;
            As[nxt][(kqA0 * 4 + 0) * 132 + mA0] = a0n.x;
            As[nxt][(kqA0 * 4 + 1) * 132 + mA0] = a0n.y;
            As[nxt][(kqA0 * 4 + 2) * 132 + mA0] = a0n.z;
            As[nxt][(kqA0 * 4 + 3) * 132 + mA0] = a0n.w;
            As[nxt][(kqA1 * 4 + 0) * 132 + mA1] = a1n.x;
            As[nxt][(kqA1 * 4 + 1) * 132 + mA1] = a1n.y;
            As[nxt][(kqA1 * 4 + 2) * 132 + mA1] = a1n.z;
            As[nxt][(kqA1 * 4 + 3) * 132 + mA1] = a1n.w;
            *(float4*)&Bs[nxt][kB * 128 + nqB * 4] = b0n;
            *(float4*)&Bs[nxt][kB * 128 + 64 + nqB * 4] = b1n;
            __syncthreads();
        }
    }
#pragma unroll
    for (int i = 0; i < 8; i++) {
        int m = m0 + ty * 8 + i;
#pragma unroll
        for (int h = 0; h < 2; h++) {
            int n = n0 + h * 64 + tx * 4;
            float4 o;
            float v0, v1, v2, v3;
            unpk(acc[i][h * 2 + 0], v0, v1);
            unpk(acc[i][h * 2 + 1], v2, v3);
            o.x = v0 + g_wbias[n + 0];
            o.y = v1 + g_wbias[n + 1];
            o.z = v2 + g_wbias[n + 2];
            o.w = v3 + g_wbias[n + 3];
            *(float4*)&g_pre[m * 1536 + n] = o;
        }
    }
}

// ---------------- persistent GRU scan: fine-grained producer waits ----------
// (FROZEN: identical to the proven round-12 kernel.)
// 4 groups x 32 CTAs; group g owns batch rows [g*16, g*16+16).
// Flags: one monotone counter per CTA: 2s+1 = z/rh written, 2s+2 = out written.
// Warp w waits only on its data producers (4 for h, 2+1 for rh/z); full
// fan-in resolves at the reduce __syncthreads. g_rh/g_z parity-buffered;
// their consumer loads use ld.global.cg (L1-bypass: address reuse).
__global__ __launch_bounds__(256, 1) void gru_scan(const float* __restrict__ h0,
                                                   float* out) {
    extern __shared__ float smem[];
    float4* hs4 = (float4*)smem;                // [16][128] chunks swizzled, 32KB
    float4* rs4 = hs4 + 2048;                   // [16][128] chunks swizzled, 32KB
    float*  us  = smem + 16384;                 // [512][32]  64KB zr weights
    float*  u2  = smem + 32768;                 // [512][16]  32KB h  weights
    u64*    red = (u64*)(smem + 40960);         // 2048 u64   16KB

    const int tid  = threadIdx.x;
    const int cta  = blockIdx.x;
    const int w    = tid >> 5;
    const int lane = tid & 31;
    const int g    = cta >> 5;
    const int cl   = cta & 31;
    const int gbase = cta & ~(GRP_CTAS - 1);
    const int gb0  = g * 16;                    // group batch base

    // --- resident weights ---
    {
        const float* up1 = g_Uzrp + cl * 16384;
#pragma unroll
        for (int i = 0; i < 16; i++) {
            int off = (i * 256 + tid) * 4;
            *(float4*)&us[off] = *(const float4*)(up1 + off);
        }
        const float* up2 = g_Uhp + cl * 8192;
#pragma unroll
        for (int i = 0; i < 8; i++) {
            int off = (i * 256 + tid) * 4;
            *(float4*)&u2[off] = *(const float4*)(up2 + off);
        }
    }

    // --- epilogue constants ---
    const int b1l = tid >> 4;                  // P1 local b (0..15)
    const int b1  = gb0 + b1l;
    const int n1  = cl * 32 + (tid & 15) * 2;  // P1 n (0..1022)
    const float2 ub1 = *(const float2*)&g_ubias[n1];
    const int o1c = b1l * 16 + ((tid & 15) ^ ((b1l >> 2) << 1));
    const int o2  = tid & 127;
    const int b2l = o2 >> 3;
    const int b2  = gb0 + b2l;
    const int n2  = cl * 16 + (o2 & 7) * 2;
    const float2 ub2 = *(const float2*)&g_ubias[1024 + n2];
    const int o2c = b2l * 8 + ((o2 & 7) ^ ((b2l >> 1) & 3));

    // --- compute-lane constants ---
    const int bg  = lane >> 3;   // P1: 4 b-groups of 4 rows
    const int ng  = lane & 7;    // P1: 8 n-groups of 4 cols
    const int bg2 = lane >> 2;   // P2: 8 b-groups of 2 rows
    const int ng2 = lane & 3;    // P2: 4 n-groups of 4 cols
    // warp-private tile-load lane map: r = q*2 + rh2, c = w*16 + wl
    const int wl  = lane & 15;
    const int rh2 = lane >> 4;
    const int cch = w * 16 + wl;

    // --- producer sets for this warp / CTA ---
    const int hprod  = gbase + w * 4;          // h producers: +0..+3
    const int rprod  = gbase + 16 + w * 2;     // rh producers: +0..+1
    const int zprod  = gbase + (cl >> 1);      // z producer for this CTA's slice

    // --- prefetch step-0 epilogue operands ---
    float2 pre1 = *(const float2*)&g_pre[b1 * 1536 + n1];
    float2 pre2 = make_float2(0.f, 0.f);
    if (tid < 128)
        pre2 = *(const float2*)&g_pre[b2 * 1536 + 1024 + n2];

    for (int s = 0; s < S_LEN; s++) {
        const float* hprev = (s == 0) ? h0 : (out + (s - 1) * (B_DIM * 512));
        const int par = s & 1;

        // ===== per-warp wait: my 4 h-producers wrote out[s-1] (>= 2s) =====
        {
            unsigned tgt = (unsigned)(2 * s);
            if (lane < 4) {
                const unsigned* fp = &g_flags[(hprod + lane) * 32];
                unsigned v;
                do {
                    asm volatile("ld.acquire.gpu.u32 %0, [%1];"
                                 : "=r"(v) : "l"(fp) : "memory");
                } while (v < tgt);
            }
            __syncwarp();
        }

        // --- warp-private load of h tile chunks [w*16, w*16+16) ---
        {
            const float4* hp4 = (const float4*)(hprev + gb0 * 512);
#pragma unroll
            for (int q = 0; q < 8; q++) {
                int r = q * 2 + rh2;
                hs4[r * 128 + swz2(r, cch)] = hp4[r * 128 + cch];
            }
            __syncwarp();
        }

        // ================= Phase 1: zr = sigmoid(pre + h@Uzr^T + ub) ========
        {
            u64 acc[4][2];
#pragma unroll
            for (int i = 0; i < 4; i++) { acc[i][0] = 0ull; acc[i][1] = 0ull; }
            const float4* hr0 = hs4 + (bg * 4 + 0) * 128;
            const float4* hr1 = hs4 + (bg * 4 + 1) * 128;
            const float4* hr2 = hs4 + (bg * 4 + 2) * 128;
            const float4* hr3 = hs4 + (bg * 4 + 3) * 128;
            const int m0 = bg * 2, m1 = (bg * 2) ^ 4;
            const int m2 = bg * 2 + 1, m3 = (bg * 2 + 1) ^ 4;
            const float* upc = us + ng * 4;
#pragma unroll
            for (int cc = 0; cc < 16; cc++) {
                int cb = w * 16 + cc;
                int cx = cb ^ w;
                float4 hv0 = hr0[cx ^ m0];
                float4 hv1 = hr1[cx ^ m1];
                float4 hv2 = hr2[cx ^ m2];
                float4 hv3 = hr3[cx ^ m3];
                const float* ub = upc + cb * 128;
                ulonglong2 uu0 = *(const ulonglong2*)(ub);
                ulonglong2 uu1 = *(const ulonglong2*)(ub + 32);
                ulonglong2 uu2 = *(const ulonglong2*)(ub + 64);
                ulonglong2 uu3 = *(const ulonglong2*)(ub + 96);
                u64 d;
                d = dupf(hv0.x); fma2(acc[0][0], d, uu0.x); fma2(acc[0][1], d, uu0.y);
                d = dupf(hv1.x); fma2(acc[1][0], d, uu0.x); fma2(acc[1][1], d, uu0.y);
                d = dupf(hv2.x); fma2(acc[2][0], d, uu0.x); fma2(acc[2][1], d, uu0.y);
                d = dupf(hv3.x); fma2(acc[3][0], d, uu0.x); fma2(acc[3][1], d, uu0.y);
                d = dupf(hv0.y); fma2(acc[0][0], d, uu1.x); fma2(acc[0][1], d, uu1.y);
                d = dupf(hv1.y); fma2(acc[1][0], d, uu1.x); fma2(acc[1][1], d, uu1.y);
                d = dupf(hv2.y); fma2(acc[2][0], d, uu1.x); fma2(acc[2][1], d, uu1.y);
                d = dupf(hv3.y); fma2(acc[3][0], d, uu1.x); fma2(acc[3][1], d, uu1.y);
                d = dupf(hv0.z); fma2(acc[0][0], d, uu2.x); fma2(acc[0][1], d, uu2.y);
                d = dupf(hv1.z); fma2(acc[1][0], d, uu2.x); fma2(acc[1][1], d, uu2.y);
                d = dupf(hv2.z); fma2(acc[2][0], d, uu2.x); fma2(acc[2][1], d, uu2.y);
                d = dupf(hv3.z); fma2(acc[3][0], d, uu2.x); fma2(acc[3][1], d, uu2.y);
                d = dupf(hv0.w); fma2(acc[0][0], d, uu3.x); fma2(acc[0][1], d, uu3.y);
                d = dupf(hv1.w); fma2(acc[1][0], d, uu3.x); fma2(acc[1][1], d, uu3.y);
                d = dupf(hv2.w); fma2(acc[2][0], d, uu3.x); fma2(acc[2][1], d, uu3.y);
                d = dupf(hv3.w); fma2(acc[3][0], d, uu3.x); fma2(acc[3][1], d, uu3.y);
            }
            int rbase = w * 256;
#pragma unroll
            for (int i = 0; i < 4; i++) {
                int bl = bg * 4 + i;
                red[rbase + bl * 16 + ((ng * 2)     ^ (bg << 1))] = acc[i][0];
                red[rbase + bl * 16 + ((ng * 2 + 1) ^ (bg << 1))] = acc[i][1];
            }
            __syncthreads();   // NOTE: implies all 32 group flags >= 2s
            {
                u64 ssum = red[o1c];
#pragma unroll
                for (int p = 1; p < 8; p++) ssum = add2(ssum, red[p * 256 + o1c]);
                float v0s, v1s; unpk(ssum, v0s, v1s);
                float a0 = pre1.x + v0s + ub1.x;
                float a1 = pre1.y + v1s + ub1.y;
                float v0 = 1.f / (1.f + __expf(-a0));
                float v1 = 1.f / (1.f + __expf(-a1));
                if (cl < 16) {
                    *(float2*)&g_z[par][b1 * 512 + n1] = make_float2(v0, v1);
                } else {
                    int j = n1 - 512;
                    int c = j >> 2;
                    const float* ch = (const float*)&hs4[b1l * 128 + swz2(b1l, c)];
                    *(float2*)&g_rh[par][b1 * 512 + j] =
                        make_float2(v0 * ch[j & 3], v1 * ch[(j & 3) + 1]);
                }
            }
        }
        __syncthreads();       // all z/rh stores done
        if (tid == 0) {
            asm volatile("st.release.gpu.u32 [%0], %1;"
                         :: "l"(&g_flags[cta * 32]), "r"((unsigned)(2 * s + 1)) : "memory");
        }

        // ===== per-warp wait: my 2 rh-producers + z-producer (>= 2s+1) =====
        {
            unsigned tgt = (unsigned)(2 * s + 1);
            if (lane < 3) {
                int p = (lane < 2) ? (rprod + lane) : zprod;
                const unsigned* fp = &g_flags[p * 32];
                unsigned v;
                do {
                    asm volatile("ld.acquire.gpu.u32 %0, [%1];"
                                 : "=r"(v) : "l"(fp) : "memory");
                } while (v < tgt);
            }
            __syncwarp();
        }

        // --- prefetch z for P2 epilogue (L1-bypass: parity-reused address) ---
        float2 zf = make_float2(0.f, 0.f);
        if (tid < 128) zf = ldcg2(&g_z[par][b2 * 512 + n2]);

        // --- warp-private load of rh tile chunks (L1-bypass) ---
        {
            const float4* rp4 = (const float4*)(g_rh[par] + gb0 * 512);
#pragma unroll
            for (int q = 0; q < 8; q++) {
                int r = q * 2 + rh2;
                rs4[r * 128 + swz2(r, cch)] = ldcg4(rp4 + r * 128 + cch);
            }
            __syncwarp();
        }

        // ================= Phase 2: h~ = tanh(pre + rh@Uh^T + ub) ===========
        {
            u64 acc[2][2];
            acc[0][0] = acc[0][1] = acc[1][0] = acc[1][1] = 0ull;
            const float4* rr0 = rs4 + (bg2 * 2 + 0) * 128;
            const float4* rr1 = rs4 + (bg2 * 2 + 1) * 128;
            const int q0 = bg2, q1 = bg2 ^ 4;
            const float* upc = u2 + ng2 * 4;
#pragma unroll
            for (int cc = 0; cc < 16; cc++) {
                int cb = w * 16 + cc;
                int cx = cb ^ w;
                float4 rv0 = rr0[cx ^ q0];
                float4 rv1 = rr1[cx ^ q1];
                const float* ub = upc + cb * 64;
                ulonglong2 uu0 = *(const ulonglong2*)(ub);
                ulonglong2 uu1 = *(const ulonglong2*)(ub + 16);
                ulonglong2 uu2 = *(const ulonglong2*)(ub + 32);
                ulonglong2 uu3 = *(const ulonglong2*)(ub + 48);
                u64 d;
                d = dupf(rv0.x); fma2(acc[0][0], d, uu0.x); fma2(acc[0][1], d, uu0.y);
                d = dupf(rv1.x); fma2(acc[1][0], d, uu0.x); fma2(acc[1][1], d, uu0.y);
                d = dupf(rv0.y); fma2(acc[0][0], d, uu1.x); fma2(acc[0][1], d, uu1.y);
                d = dupf(rv1.y); fma2(acc[1][0], d, uu1.x); fma2(acc[1][1], d, uu1.y);
                d = dupf(rv0.z); fma2(acc[0][0], d, uu2.x); fma2(acc[0][1], d, uu2.y);
                d = dupf(rv1.z); fma2(acc[1][0], d, uu2.x); fma2(acc[1][1], d, uu2.y);
                d = dupf(rv0.w); fma2(acc[0][0], d, uu3.x); fma2(acc[0][1], d, uu3.y);
                d = dupf(rv1.w); fma2(acc[1][0], d, uu3.x); fma2(acc[1][1], d, uu3.y);
            }
            int rbase = w * 128;
#pragma unroll
            for (int i = 0; i < 2; i++) {
                int bl = bg2 * 2 + i;
                red[rbase + bl * 8 + ((ng2 * 2)     ^ (bg2 & 3))] = acc[i][0];
                red[rbase + bl * 8 + ((ng2 * 2 + 1) ^ (bg2 & 3))] = acc[i][1];
            }
            __syncthreads();
            if (tid < 128) {
                u64 ssum = red[o2c];
#pragma unroll
                for (int p = 1; p < 8; p++) ssum = add2(ssum, red[p * 128 + o2c]);
                float v0s, v1s; unpk(ssum, v0s, v1s);
                int c = n2 >> 2;
                const float* ch = (const float*)&hs4[b2l * 128 + swz2(b2l, c)];
                float hp0 = ch[n2 & 3], hp1 = ch[(n2 & 3) + 1];
                float a0 = pre2.x + v0s + ub2.x;
                float a1 = pre2.y + v1s + ub2.y;
                float e0 = __expf(2.f * a0), e1 = __expf(2.f * a1);
                float th0 = 1.f - 2.f / (e0 + 1.f);
                float th1 = 1.f - 2.f / (e1 + 1.f);
                float hn0 = hp0 + zf.x * (th0 - hp0);
                float hn1 = hp1 + zf.y * (th1 - hp1);
                float2 o = make_float2(hn0, hn1);
                *(float2*)&out[s * (B_DIM * 512) + b2 * 512 + n2] = o;
                if (s == S_LEN - 1)
                    *(float2*)&out[S_LEN * (B_DIM * 512) + b2 * 512 + n2] = o;
            }
        }
        __syncthreads();       // out stores + hs4/rs4 epilogue reads done
        if (tid == 0) {
            asm volatile("st.release.gpu.u32 [%0], %1;"
                         :: "l"(&g_flags[cta * 32]), "r"((unsigned)(2 * s + 2)) : "memory");
        }
        // next-step epilogue prefetch in the release/wait shadow
        {
            int sp = (s + 1 < S_LEN) ? (s + 1) : s;
            pre1 = *(const float2*)&g_pre[(sp * 64 + b1) * 1536 + n1];
            if (tid < 128)
                pre2 = *(const float2*)&g_pre[(sp * 64 + b2) * 1536 + 1024 + n2];
        }
    }
}

// ---------------- launch ----------------------------------------------------
extern "C" void kernel_launch(void* const* d_in, const int* in_sizes, int n_in,
                              void* d_out, int out_size) {
    (void)in_sizes; (void)n_in; (void)out_size;
    const float* x    = (const float*)d_in[0];
    const float* h0   = (const float*)d_in[1];
    const float* Wz_w = (const float*)d_in[2];
    const float* Wz_b = (const float*)d_in[3];
    const float* Uz_w = (const float*)d_in[4];
    const float* Uz_b = (const float*)d_in[5];
    const float* Wr_w = (const float*)d_in[6];
    const float* Wr_b = (const float*)d_in[7];
    const float* Ur_w = (const float*)d_in[8];
    const float* Ur_b = (const float*)d_in[9];
    const float* Wh_w = (const float*)d_in[10];
    const float* Wh_b = (const float*)d_in[11];
    const float* Uh_w = (const float*)d_in[12];
    const float* Uh_b = (const float*)d_in[13];
    float* out = (float*)d_out;

    static int smem_set = 0;
    if (!smem_set) {
        cudaFuncSetAttribute(gru_scan, cudaFuncAttributeMaxDynamicSharedMemorySize,
                             180224);
        smem_set = 1;
    }

    pack_kernel<<<256, 256>>>(Wz_w, Wz_b, Uz_w, Uz_b,
                              Wr_w, Wr_b, Ur_w, Ur_b,
                              Wh_w, Wh_b, Uh_w, Uh_b);
    input_gemm<<<dim3(12, 512), 256>>>(x);
    gru_scan<<<NBLK, 256, 180224>>>(h0, out);
}

// round 15
// speedup vs baseline: 1.0436x; 1.0102x over previous
#include <cuda_runtime.h>
#include <math.h>

#define S_LEN 1024
#define B_DIM 64
#define NBLK  128
#define GRP_CTAS 32

typedef unsigned long long u64;

// ---------------- f32x2 helpers (sm_100+) -----------------------------------
__device__ __forceinline__ u64 dupf(float x) {
    u64 r; unsigned xi = __float_as_uint(x);
    asm("mov.b64 %0, {%1, %1};" : "=l"(r) : "r"(xi));
    return r;
}
__device__ __forceinline__ void fma2(u64& d, u64 a, u64 b) {
    asm("fma.rn.f32x2 %0, %1, %2, %0;" : "+l"(d) : "l"(a), "l"(b));
}
__device__ __forceinline__ u64 add2(u64 a, u64 b) {
    u64 d; asm("add.rn.f32x2 %0, %1, %2;" : "=l"(d) : "l"(a), "l"(b));
    return d;
}
__device__ __forceinline__ void unpk(u64 p, float& lo, float& hi) {
    unsigned a, b;
    asm("mov.b64 {%0, %1}, %2;" : "=r"(a), "=r"(b) : "l"(p));
    lo = __uint_as_float(a); hi = __uint_as_float(b);
}

// swizzled chunk column for 16-row tiles
__device__ __forceinline__ int swz2(int b, int c) {
    return c ^ ((b >> 1) & 7) ^ ((c >> 4) & 7) ^ ((b & 1) << 2);
}

// L1-bypassing accesses for cross-CTA-communicated globals
__device__ __forceinline__ float4 ldcg4(const float4* p) {
    float4 v;
    asm volatile("ld.global.cg.v4.f32 {%0,%1,%2,%3}, [%4];"
                 : "=f"(v.x), "=f"(v.y), "=f"(v.z), "=f"(v.w) : "l"(p));
    return v;
}
__device__ __forceinline__ float2 ldcg2(const float* p) {
    float2 v;
    asm volatile("ld.global.cg.v2.f32 {%0,%1}, [%2];"
                 : "=f"(v.x), "=f"(v.y) : "l"(p));
    return v;
}
__device__ __forceinline__ void stcg2(float* p, float2 v) {
    asm volatile("st.global.cg.v2.f32 [%0], {%1,%2};"
                 :: "l"(p), "f"(v.x), "f"(v.y) : "memory");
}

// ---------------- device scratch --------------------------------------------
__device__ float g_pre[S_LEN * B_DIM * 1536];   // xz|xr|xh preactivations
__device__ float g_WT[512 * 1536];              // [k][n] input weights (k-major)
__device__ float g_Uzrp[32 * 512 * 32];         // packed [cl][k][32n] zr weights
__device__ float g_Uhp[32 * 512 * 16];          // packed [cl][k][16n] h weights
__device__ float g_wbias[1536];
__device__ float g_ubias[1536];
__device__ float g_z[2][B_DIM * 512];           // parity-buffered gate values
__device__ float g_rh[2][B_DIM * 512];
__device__ unsigned g_flags[NBLK * 32];         // per-CTA flags, 128B stride

// ---------------- pack + flag reset -----------------------------------------
__global__ void pack_kernel(const float* Wz, const float* bz, const float* Uz, const float* ubz,
                            const float* Wr, const float* br, const float* Ur, const float* ubr,
                            const float* Wh, const float* bh, const float* Uh, const float* ubh) {
    int stride = gridDim.x * blockDim.x;
    int t = blockIdx.x * blockDim.x + threadIdx.x;
    for (int idx = t; idx < NBLK * 32; idx += stride) g_flags[idx] = 0u;
    for (int idx = t; idx < 512 * 1536; idx += stride) {
        int k = idx / 1536, n = idx % 1536;
        const float* W = (n < 512) ? Wz : (n < 1024 ? Wr : Wh);
        g_WT[idx] = W[(n & 511) * 512 + k];
    }
    for (int idx = t; idx < 32 * 512 * 32; idx += stride) {
        int cl = idx >> 14, k = (idx >> 5) & 511, nn = idx & 31;
        int n = cl * 32 + nn;
        g_Uzrp[idx] = (n < 512) ? Uz[n * 512 + k] : Ur[(n - 512) * 512 + k];
    }
    for (int idx = t; idx < 32 * 512 * 16; idx += stride) {
        int cl = idx >> 13, k = (idx >> 4) & 511, nn = idx & 15;
        g_Uhp[idx] = Uh[(cl * 16 + nn) * 512 + k];
    }
    for (int idx = t; idx < 1536; idx += stride) {
        int n = idx & 511;
        g_wbias[idx] = (idx < 512) ? bz[n] : (idx < 1024 ? br[n] : bh[n]);
        g_ubias[idx] = (idx < 512) ? ubz[n] : (idx < 1024 ? ubr[n] : ubh[n]);
    }
}

// ---------------- input projection GEMM (f32x2, double-buffered, BN=128) ----
__global__ __launch_bounds__(256, 2) void input_gemm(const float* __restrict__ x) {
    __shared__ float As[2][16 * 132];
    __shared__ float Bs[2][16 * 128];
    int tid = threadIdx.x;
    int tx = tid & 15, ty = tid >> 4;
    int m0 = blockIdx.y * 128;
    int n0 = blockIdx.x * 128;

    const int fA0 = tid,       mA0 = fA0 >> 2, kqA0 = fA0 & 3;
    const int fA1 = 256 + tid, mA1 = fA1 >> 2, kqA1 = fA1 & 3;
    const int kB  = tid >> 4,  nqB = tid & 15;
    const float* xA0 = x + (m0 + mA0) * 512 + kqA0 * 4;
    const float* xA1 = x + (m0 + mA1) * 512 + kqA1 * 4;
    const float* wB0 = g_WT + kB * 1536 + n0 + nqB * 4;
    const float* wB1 = wB0 + 64;

    u64 acc[8][4];
#pragma unroll
    for (int i = 0; i < 8; i++)
#pragma unroll
        for (int j = 0; j < 4; j++) acc[i][j] = 0ull;

    {
        float4 a0 = *(const float4*)(xA0);
        float4 a1 = *(const float4*)(xA1);
        float4 b0 = *(const float4*)(wB0);
        float4 b1 = *(const float4*)(wB1);
        As[0][(kqA0 * 4 + 0) * 132 + mA0] = a0.x;
        As[0][(kqA0 * 4 + 1) * 132 + mA0] = a0.y;
        As[0][(kqA0 * 4 + 2) * 132 + mA0] = a0.z;
        As[0][(kqA0 * 4 + 3) * 132 + mA0] = a0.w;
        As[0][(kqA1 * 4 + 0) * 132 + mA1] = a1.x;
        As[0][(kqA1 * 4 + 1) * 132 + mA1] = a1.y;
        As[0][(kqA1 * 4 + 2) * 132 + mA1] = a1.z;
        As[0][(kqA1 * 4 + 3) * 132 + mA1] = a1.w;
        *(float4*)&Bs[0][kB * 128 + nqB * 4] = b0;
        *(float4*)&Bs[0][kB * 128 + 64 + nqB * 4] = b1;
    }
    __syncthreads();

    for (int kt = 0; kt < 32; kt++) {
        int cur = kt & 1;
        float4 a0n, a1n, b0n, b1n;
        if (kt < 31) {
            int k0 = (kt + 1) * 16;
            a0n = *(const float4*)(xA0 + k0);
            a1n = *(const float4*)(xA1 + k0);
            b0n = *(const float4*)(wB0 + (unsigned)k0 * 1536);
            b1n = *(const float4*)(wB1 + (unsigned)k0 * 1536);
        }
        const float* Ac = As[cur];
        const float* Bc = Bs[cur];
#pragma unroll
        for (int kk = 0; kk < 16; kk++) {
            float4 a0 = *(const float4*)&Ac[kk * 132 + ty * 8];
            float4 a1 = *(const float4*)&Ac[kk * 132 + ty * 8 + 4];
            ulonglong2 bb0 = *(const ulonglong2*)&Bc[kk * 128 + tx * 4];
            ulonglong2 bb1 = *(const ulonglong2*)&Bc[kk * 128 + 64 + tx * 4];
            u64 d0 = dupf(a0.x), d1 = dupf(a0.y), d2 = dupf(a0.z), d3 = dupf(a0.w);
            u64 d4 = dupf(a1.x), d5 = dupf(a1.y), d6 = dupf(a1.z), d7 = dupf(a1.w);
            fma2(acc[0][0], d0, bb0.x); fma2(acc[0][1], d0, bb0.y);
            fma2(acc[1][0], d1, bb0.x); fma2(acc[1][1], d1, bb0.y);
            fma2(acc[2][0], d2, bb0.x); fma2(acc[2][1], d2, bb0.y);
            fma2(acc[3][0], d3, bb0.x); fma2(acc[3][1], d3, bb0.y);
            fma2(acc[4][0], d4, bb0.x); fma2(acc[4][1], d4, bb0.y);
            fma2(acc[5][0], d5, bb0.x); fma2(acc[5][1], d5, bb0.y);
            fma2(acc[6][0], d6, bb0.x); fma2(acc[6][1], d6, bb0.y);
            fma2(acc[7][0], d7, bb0.x); fma2(acc[7][1], d7, bb0.y);
            fma2(acc[0][2], d0, bb1.x); fma2(acc[0][3], d0, bb1.y);
            fma2(acc[1][2], d1, bb1.x); fma2(acc[1][3], d1, bb1.y);
            fma2(acc[2][2], d2, bb1.x); fma2(acc[2][3], d2, bb1.y);
            fma2(acc[3][2], d3, bb1.x); fma2(acc[3][3], d3, bb1.y);
            fma2(acc[4][2], d4, bb1.x); fma2(acc[4][3], d4, bb1.y);
            fma2(acc[5][2], d5, bb1.x); fma2(acc[5][3], d5, bb1.y);
            fma2(acc[6][2], d6, bb1.x); fma2(acc[6][3], d6, bb1.y);
            fma2(acc[7][2], d7, bb1.x); fma2(acc[7][3], d7, bb1.y);
        }
        if (kt < 31) {
            int nxt = cur ^ 1;
            As[nxt][(kqA0 * 4 + 0) * 132 + mA0] = a0n.x;
            As[nxt][(kqA0 * 4 + 1) * 132 + mA0] = a0n.y;
            As[nxt][(kqA0 * 4 + 2) * 132 + mA0] = a0n.z;
            As[nxt][(kqA0 * 4 + 3) * 132 + mA0] = a0n.w;
            As[nxt][(kqA1 * 4 + 0) * 132 + mA1] = a1n.x;
            As[nxt][(kqA1 * 4 + 1) * 132 + mA1] = a1n.y;
            As[nxt][(kqA1 * 4 + 2) * 132 + mA1] = a1n.z;
            As[nxt][(kqA1 * 4 + 3) * 132 + mA1] = a1n.w;
            *(float4*)&Bs[nxt][kB * 128 + nqB * 4] = b0n;
            *(float4*)&Bs[nxt][kB * 128 + 64 + nqB * 4] = b1n;
            __syncthreads();
        }
    }
#pragma unroll
    for (int i = 0; i < 8; i++) {
        int m = m0 + ty * 8 + i;
#pragma unroll
        for (int h = 0; h < 2; h++) {
            int n = n0 + h * 64 + tx * 4;
            float4 o;
            float v0, v1, v2, v3;
            unpk(acc[i][h * 2 + 0], v0, v1);
            unpk(acc[i][h * 2 + 1], v2, v3);
            o.x = v0 + g_wbias[n + 0];
            o.y = v1 + g_wbias[n + 1];
            o.z = v2 + g_wbias[n + 2];
            o.w = v3 + g_wbias[n + 3];
            *(float4*)&g_pre[m * 1536 + n] = o;
        }
    }
}

// ---------------- persistent GRU scan: fine-grained producer waits ----------
// 4 groups x 32 CTAs; group g owns batch rows [g*16, g*16+16).
// Flags: one monotone counter per CTA: 2s+1 = z/rh written, 2s+2 = out written.
// ALL cross-CTA data (out, g_rh, g_z) moves strictly through L2: .cg loads
// AND .cg stores, eliminating stale-L1 lines (incl. the half-line
// write-allocate channel on out rows shared between adjacent slices).
__global__ __launch_bounds__(256, 1) void gru_scan(const float* __restrict__ h0,
                                                   float* out) {
    extern __shared__ float smem[];
    float4* hs4 = (float4*)smem;                // [16][128] chunks swizzled, 32KB
    float4* rs4 = hs4 + 2048;                   // [16][128] chunks swizzled, 32KB
    float*  us  = smem + 16384;                 // [512][32]  64KB zr weights
    float*  u2  = smem + 32768;                 // [512][16]  32KB h  weights
    u64*    red = (u64*)(smem + 40960);         // 2048 u64   16KB

    const int tid  = threadIdx.x;
    const int cta  = blockIdx.x;
    const int w    = tid >> 5;
    const int lane = tid & 31;
    const int g    = cta >> 5;
    const int cl   = cta & 31;
    const int gbase = cta & ~(GRP_CTAS - 1);
    const int gb0  = g * 16;                    // group batch base

    // --- resident weights ---
    {
        const float* up1 = g_Uzrp + cl * 16384;
#pragma unroll
        for (int i = 0; i < 16; i++) {
            int off = (i * 256 + tid) * 4;
            *(float4*)&us[off] = *(const float4*)(up1 + off);
        }
        const float* up2 = g_Uhp + cl * 8192;
#pragma unroll
        for (int i = 0; i < 8; i++) {
            int off = (i * 256 + tid) * 4;
            *(float4*)&u2[off] = *(const float4*)(up2 + off);
        }
    }

    // --- epilogue constants ---
    const int b1l = tid >> 4;                  // P1 local b (0..15)
    const int b1  = gb0 + b1l;
    const int n1  = cl * 32 + (tid & 15) * 2;  // P1 n (0..1022)
    const float2 ub1 = *(const float2*)&g_ubias[n1];
    const int o1c = b1l * 16 + ((tid & 15) ^ ((b1l >> 2) << 1));
    const int o2  = tid & 127;
    const int b2l = o2 >> 3;
    const int b2  = gb0 + b2l;
    const int n2  = cl * 16 + (o2 & 7) * 2;
    const float2 ub2 = *(const float2*)&g_ubias[1024 + n2];
    const int o2c = b2l * 8 + ((o2 & 7) ^ ((b2l >> 1) & 3));

    // --- compute-lane constants ---
    const int bg  = lane >> 3;   // P1: 4 b-groups of 4 rows
    const int ng  = lane & 7;    // P1: 8 n-groups of 4 cols
    const int bg2 = lane >> 2;   // P2: 8 b-groups of 2 rows
    const int ng2 = lane & 3;    // P2: 4 n-groups of 4 cols
    // warp-private tile-load lane map: r = q*2 + rh2, c = w*16 + wl
    const int wl  = lane & 15;
    const int rh2 = lane >> 4;
    const int cch = w * 16 + wl;

    // --- producer sets for this warp / CTA ---
    const int hprod  = gbase + w * 4;          // h producers: +0..+3
    const int rprod  = gbase + 16 + w * 2;     // rh producers: +0..+1
    const int zprod  = gbase + (cl >> 1);      // z producer for this CTA's slice

    // --- prefetch step-0 epilogue operands ---
    float2 pre1 = *(const float2*)&g_pre[b1 * 1536 + n1];
    float2 pre2 = make_float2(0.f, 0.f);
    if (tid < 128)
        pre2 = *(const float2*)&g_pre[b2 * 1536 + 1024 + n2];

    for (int s = 0; s < S_LEN; s++) {
        const float* hprev = (s == 0) ? h0 : (out + (s - 1) * (B_DIM * 512));
        const int par = s & 1;

        // ===== per-warp wait: my 4 h-producers wrote out[s-1] (>= 2s) =====
        {
            unsigned tgt = (unsigned)(2 * s);
            if (lane < 4) {
                const unsigned* fp = &g_flags[(hprod + lane) * 32];
                unsigned v;
                do {
                    asm volatile("ld.acquire.gpu.u32 %0, [%1];"
                                 : "=r"(v) : "l"(fp) : "memory");
                } while (v < tgt);
            }
            __syncwarp();
        }

        // --- warp-private load of h tile chunks (L1-bypass: cross-CTA data) ---
        {
            const float4* hp4 = (const float4*)(hprev + gb0 * 512);
#pragma unroll
            for (int q = 0; q < 8; q++) {
                int r = q * 2 + rh2;
                hs4[r * 128 + swz2(r, cch)] = ldcg4(hp4 + r * 128 + cch);
            }
            __syncwarp();
        }

        // ================= Phase 1: zr = sigmoid(pre + h@Uzr^T + ub) ========
        {
            u64 acc[4][2];
#pragma unroll
            for (int i = 0; i < 4; i++) { acc[i][0] = 0ull; acc[i][1] = 0ull; }
            const float4* hr0 = hs4 + (bg * 4 + 0) * 128;
            const float4* hr1 = hs4 + (bg * 4 + 1) * 128;
            const float4* hr2 = hs4 + (bg * 4 + 2) * 128;
            const float4* hr3 = hs4 + (bg * 4 + 3) * 128;
            const int m0 = bg * 2, m1 = (bg * 2) ^ 4;
            const int m2 = bg * 2 + 1, m3 = (bg * 2 + 1) ^ 4;
            const float* upc = us + ng * 4;
#pragma unroll
            for (int cc = 0; cc < 16; cc++) {
                int cb = w * 16 + cc;
                int cx = cb ^ w;
                float4 hv0 = hr0[cx ^ m0];
                float4 hv1 = hr1[cx ^ m1];
                float4 hv2 = hr2[cx ^ m2];
                float4 hv3 = hr3[cx ^ m3];
                const float* ub = upc + cb * 128;
                ulonglong2 uu0 = *(const ulonglong2*)(ub);
                ulonglong2 uu1 = *(const ulonglong2*)(ub + 32);
                ulonglong2 uu2 = *(const ulonglong2*)(ub + 64);
                ulonglong2 uu3 = *(const ulonglong2*)(ub + 96);
                u64 d;
                d = dupf(hv0.x); fma2(acc[0][0], d, uu0.x); fma2(acc[0][1], d, uu0.y);
                d = dupf(hv1.x); fma2(acc[1][0], d, uu0.x); fma2(acc[1][1], d, uu0.y);
                d = dupf(hv2.x); fma2(acc[2][0], d, uu0.x); fma2(acc[2][1], d, uu0.y);
                d = dupf(hv3.x); fma2(acc[3][0], d, uu0.x); fma2(acc[3][1], d, uu0.y);
                d = dupf(hv0.y); fma2(acc[0][0], d, uu1.x); fma2(acc[0][1], d, uu1.y);
                d = dupf(hv1.y); fma2(acc[1][0], d, uu1.x); fma2(acc[1][1], d, uu1.y);
                d = dupf(hv2.y); fma2(acc[2][0], d, uu1.x); fma2(acc[2][1], d, uu1.y);
                d = dupf(hv3.y); fma2(acc[3][0], d, uu1.x); fma2(acc[3][1], d, uu1.y);
                d = dupf(hv0.z); fma2(acc[0][0], d, uu2.x); fma2(acc[0][1], d, uu2.y);
                d = dupf(hv1.z); fma2(acc[1][0], d, uu2.x); fma2(acc[1][1], d, uu2.y);
                d = dupf(hv2.z); fma2(acc[2][0], d, uu2.x); fma2(acc[2][1], d, uu2.y);
                d = dupf(hv3.z); fma2(acc[3][0], d, uu2.x); fma2(acc[3][1], d, uu2.y);
                d = dupf(hv0.w); fma2(acc[0][0], d, uu3.x); fma2(acc[0][1], d, uu3.y);
                d = dupf(hv1.w); fma2(acc[1][0], d, uu3.x); fma2(acc[1][1], d, uu3.y);
                d = dupf(hv2.w); fma2(acc[2][0], d, uu3.x); fma2(acc[2][1], d, uu3.y);
                d = dupf(hv3.w); fma2(acc[3][0], d, uu3.x); fma2(acc[3][1], d, uu3.y);
            }
            int rbase = w * 256;
#pragma unroll
            for (int i = 0; i < 4; i++) {
                int bl = bg * 4 + i;
                red[rbase + bl * 16 + ((ng * 2)     ^ (bg << 1))] = acc[i][0];
                red[rbase + bl * 16 + ((ng * 2 + 1) ^ (bg << 1))] = acc[i][1];
            }
            __syncthreads();   // NOTE: implies all 32 group flags >= 2s
            {
                u64 ssum = red[o1c];
#pragma unroll
                for (int p = 1; p < 8; p++) ssum = add2(ssum, red[p * 256 + o1c]);
                float v0s, v1s; unpk(ssum, v0s, v1s);
                float a0 = pre1.x + v0s + ub1.x;
                float a1 = pre1.y + v1s + ub1.y;
                float v0 = 1.f / (1.f + __expf(-a0));
                float v1 = 1.f / (1.f + __expf(-a1));
                if (cl < 16) {
                    stcg2(&g_z[par][b1 * 512 + n1], make_float2(v0, v1));
                } else {
                    int j = n1 - 512;
                    int c = j >> 2;
                    const float* ch = (const float*)&hs4[b1l * 128 + swz2(b1l, c)];
                    stcg2(&g_rh[par][b1 * 512 + j],
                          make_float2(v0 * ch[j & 3], v1 * ch[(j & 3) + 1]));
                }
            }
        }
        __syncthreads();       // all z/rh stores done
        if (tid == 0) {
            asm volatile("st.release.gpu.u32 [%0], %1;"
                         :: "l"(&g_flags[cta * 32]), "r"((unsigned)(2 * s + 1)) : "memory");
        }

        // ===== per-warp wait: my 2 rh-producers + z-producer (>= 2s+1) =====
        {
            unsigned tgt = (unsigned)(2 * s + 1);
            if (lane < 3) {
                int p = (lane < 2) ? (rprod + lane) : zprod;
                const unsigned* fp = &g_flags[p * 32];
                unsigned v;
                do {
                    asm volatile("ld.acquire.gpu.u32 %0, [%1];"
                                 : "=r"(v) : "l"(fp) : "memory");
                } while (v < tgt);
            }
            __syncwarp();
        }

        // --- prefetch z for P2 epilogue (L1-bypass) ---
        float2 zf = make_float2(0.f, 0.f);
        if (tid < 128) zf = ldcg2(&g_z[par][b2 * 512 + n2]);

        // --- warp-private load of rh tile chunks (L1-bypass) ---
        {
            const float4* rp4 = (const float4*)(g_rh[par] + gb0 * 512);
#pragma unroll
            for (int q = 0; q < 8; q++) {
                int r = q * 2 + rh2;
                rs4[r * 128 + swz2(r, cch)] = ldcg4(rp4 + r * 128 + cch);
            }
            __syncwarp();
        }

        // ================= Phase 2: h~ = tanh(pre + rh@Uh^T + ub) ===========
        {
            u64 acc[2][2];
            acc[0][0] = acc[0][1] = acc[1][0] = acc[1][1] = 0ull;
            const float4* rr0 = rs4 + (bg2 * 2 + 0) * 128;
            const float4* rr1 = rs4 + (bg2 * 2 + 1) * 128;
            const int q0 = bg2, q1 = bg2 ^ 4;
            const float* upc = u2 + ng2 * 4;
#pragma unroll
            for (int cc = 0; cc < 16; cc++) {
                int cb = w * 16 + cc;
                int cx = cb ^ w;
                float4 rv0 = rr0[cx ^ q0];
                float4 rv1 = rr1[cx ^ q1];
                const float* ub = upc + cb * 64;
                ulonglong2 uu0 = *(const ulonglong2*)(ub);
                ulonglong2 uu1 = *(const ulonglong2*)(ub + 16);
                ulonglong2 uu2 = *(const ulonglong2*)(ub + 32);
                ulonglong2 uu3 = *(const ulonglong2*)(ub + 48);
                u64 d;
                d = dupf(rv0.x); fma2(acc[0][0], d, uu0.x); fma2(acc[0][1], d, uu0.y);
                d = dupf(rv1.x); fma2(acc[1][0], d, uu0.x); fma2(acc[1][1], d, uu0.y);
                d = dupf(rv0.y); fma2(acc[0][0], d, uu1.x); fma2(acc[0][1], d, uu1.y);
                d = dupf(rv1.y); fma2(acc[1][0], d, uu1.x); fma2(acc[1][1], d, uu1.y);
                d = dupf(rv0.z); fma2(acc[0][0], d, uu2.x); fma2(acc[0][1], d, uu2.y);
                d = dupf(rv1.z); fma2(acc[1][0], d, uu2.x); fma2(acc[1][1], d, uu2.y);
                d = dupf(rv0.w); fma2(acc[0][0], d, uu3.x); fma2(acc[0][1], d, uu3.y);
                d = dupf(rv1.w); fma2(acc[1][0], d, uu3.x); fma2(acc[1][1], d, uu3.y);
            }
            int rbase = w * 128;
#pragma unroll
            for (int i = 0; i < 2; i++) {
                int bl = bg2 * 2 + i;
                red[rbase + bl * 8 + ((ng2 * 2)     ^ (bg2 & 3))] = acc[i][0];
                red[rbase + bl * 8 + ((ng2 * 2 + 1) ^ (bg2 & 3))] = acc[i][1];
            }
            __syncthreads();
            if (tid < 128) {
                u64 ssum = red[o2c];
#pragma unroll
                for (int p = 1; p < 8; p++) ssum = add2(ssum, red[p * 128 + o2c]);
                float v0s, v1s; unpk(ssum, v0s, v1s);
                int c = n2 >> 2;
                const float* ch = (const float*)&hs4[b2l * 128 + swz2(b2l, c)];
                float hp0 = ch[n2 & 3], hp1 = ch[(n2 & 3) + 1];
                float a0 = pre2.x + v0s + ub2.x;
                float a1 = pre2.y + v1s + ub2.y;
                float e0 = __expf(2.f * a0), e1 = __expf(2.f * a1);
                float th0 = 1.f - 2.f / (e0 + 1.f);
                float th1 = 1.f - 2.f / (e1 + 1.f);
                float hn0 = hp0 + zf.x * (th0 - hp0);
                float hn1 = hp1 + zf.y * (th1 - hp1);
                float2 o = make_float2(hn0, hn1);
                stcg2(&out[s * (B_DIM * 512) + b2 * 512 + n2], o);
                if (s == S_LEN - 1)
                    stcg2(&out[S_LEN * (B_DIM * 512) + b2 * 512 + n2], o);
            }
        }
        __syncthreads();       // out stores + hs4/rs4 epilogue reads done
        if (tid == 0) {
            asm volatile("st.release.gpu.u32 [%0], %1;"
                         :: "l"(&g_flags[cta * 32]), "r"((unsigned)(2 * s + 2)) : "memory");
        }
        // next-step epilogue prefetch in the release/wait shadow
        {
            int sp = (s + 1 < S_LEN) ? (s + 1) : s;
            pre1 = *(const float2*)&g_pre[(sp * 64 + b1) * 1536 + n1];
            if (tid < 128)
                pre2 = *(const float2*)&g_pre[(sp * 64 + b2) * 1536 + 1024 + n2];
        }
    }
}

// ---------------- launch ----------------------------------------------------
extern "C" void kernel_launch(void* const* d_in, const int* in_sizes, int n_in,
                              void* d_out, int out_size) {
    (void)in_sizes; (void)n_in; (void)out_size;
    const float* x    = (const float*)d_in[0];
    const float* h0   = (const float*)d_in[1];
    const float* Wz_w = (const float*)d_in[2];
    const float* Wz_b = (const float*)d_in[3];
    const float* Uz_w = (const float*)d_in[4];
    const float* Uz_b = (const float*)d_in[5];
    const float* Wr_w = (const float*)d_in[6];
    const float* Wr_b = (const float*)d_in[7];
    const float* Ur_w = (const float*)d_in[8];
    const float* Ur_b = (const float*)d_in[9];
    const float* Wh_w = (const float*)d_in[10];
    const float* Wh_b = (const float*)d_in[11];
    const float* Uh_w = (const float*)d_in[12];
    const float* Uh_b = (const float*)d_in[13];
    float* out = (float*)d_out;

    static int smem_set = 0;
    if (!smem_set) {
        cudaFuncSetAttribute(gru_scan, cudaFuncAttributeMaxDynamicSharedMemorySize,
                             180224);
        smem_set = 1;
    }

    pack_kernel<<<256, 256>>>(Wz_w, Wz_b, Uz_w, Uz_b,
                              Wr_w, Wr_b, Ur_w, Ur_b,
                              Wh_w, Wh_b, Uh_w, Uh_b);
    input_gemm<<<dim3(12, 512), 256>>>(x);
    gru_scan<<<NBLK, 256, 180224>>>(h0, out);
}